// round 9
// baseline (speedup 1.0000x reference)
#include <cuda_runtime.h>
#include <cuda_bf16.h>
#include <cuda_fp16.h>
#include <cstdint>

// ============================================================================
// HQQ grouped int4 GEMM, sm_103 base target, mma.sync fp16 path.
//
// W = q*s + zp (zp = z - 8s).  Per quant group g (K-chunk of 64):
//   mast  += x_f16 @ (q*s)_f16   (s folded into B at dequant; fp32 accum)
//   out   += R @ Z^T             (rank-32 zero-point correction, bf16 hi/lo)
//
// R9: CTA 256 thr, tile 64x128, 2 CTAs/SM. K-SPLIT warps: wk=wid>>2 owns
// half the k-chunk with a 64x32 warp tile (fewer ldsm per MMA); one SMEM
// combine at the end merges the two k-halves.
// ============================================================================

namespace {

constexpr int kE   = 8;
constexpr int kIN  = 2048;
constexpr int kOUT = 2048;
constexpr int kG   = 32;

constexpr int kBM  = 64;
constexpr int kBN  = 128;
constexpr int kBK  = 64;                  // == group size
constexpr int kNCh = kIN / kBK;           // 32
constexpr int kThreads = 256;             // 8 warps: wk = wid>>2, wn = wid&3

constexpr int kATileB = kBM * kBK * 2;    // 8 KB
constexpr int kBTileB = kBN * kBK * 2;    // 16 KB
constexpr int kStageB = kATileB + kBTileB;           // 24576
constexpr int kRZoff  = 2 * kStageB;                 // 49152
constexpr int kRhOff = kRZoff;                       // R_hi 4KB (64 x 32 bf16)
constexpr int kRlOff = kRZoff + 4096;                // R_lo 4KB
constexpr int kZhOff = kRZoff + 8192;                // Z_hi 8KB (128 x 32)
constexpr int kZlOff = kRZoff + 16384;               // Z_lo 8KB
constexpr int kSmemB = kRZoff + 24576;               // 73728
// combine scratch overlays the stage buffers: 8 tiles of 32x32 f32 (4KB each)

// ---------------------------------------------------------------------------

__device__ __forceinline__ uint32_t smem_u32(const void* p) {
  uint32_t a;
  asm("{ .reg .u64 t; cvta.to.shared.u64 t, %1; cvt.u32.u64 %0, t; }" : "=r"(a) : "l"(p));
  return a;
}

__device__ __forceinline__ uint32_t pack_f16x2(float lo, float hi) {
  uint32_t r;
  asm("cvt.rn.f16x2.f32 %0, %1, %2;" : "=r"(r) : "f"(hi), "f"(lo));
  return r;
}

__device__ __forceinline__ uint32_t sw128(uint32_t off) {
  return off ^ ((off >> 3) & 0x70);
}

__device__ __forceinline__ void ldsm_x4(uint32_t* r, uint32_t addr) {
  asm volatile("ldmatrix.sync.aligned.m8n8.x4.shared.b16 {%0,%1,%2,%3}, [%4];"
               : "=r"(r[0]), "=r"(r[1]), "=r"(r[2]), "=r"(r[3]) : "r"(addr));
}

__device__ __forceinline__ void ldsm_x2(uint32_t* r, uint32_t addr) {
  asm volatile("ldmatrix.sync.aligned.m8n8.x2.shared.b16 {%0,%1}, [%2];"
               : "=r"(r[0]), "=r"(r[1]) : "r"(addr));
}

__device__ __forceinline__ void mma_f16(float* c, const uint32_t* a,
                                        uint32_t b0, uint32_t b1) {
  asm volatile(
      "mma.sync.aligned.m16n8k16.row.col.f32.f16.f16.f32 "
      "{%0,%1,%2,%3}, {%4,%5,%6,%7}, {%8,%9}, {%0,%1,%2,%3};"
      : "+f"(c[0]), "+f"(c[1]), "+f"(c[2]), "+f"(c[3])
      : "r"(a[0]), "r"(a[1]), "r"(a[2]), "r"(a[3]), "r"(b0), "r"(b1));
}

__device__ __forceinline__ void mma_bf16(float* c, const uint32_t* a, const uint32_t* b) {
  asm volatile(
      "mma.sync.aligned.m16n8k16.row.col.f32.bf16.bf16.f32 "
      "{%0,%1,%2,%3}, {%4,%5,%6,%7}, {%8,%9}, {%0,%1,%2,%3};"
      : "+f"(c[0]), "+f"(c[1]), "+f"(c[2]), "+f"(c[3])
      : "r"(a[0]), "r"(a[1]), "r"(a[2]), "r"(a[3]), "r"(b[0]), "r"(b[1]));
}

__device__ __forceinline__ uint32_t pack4b(int a, int b, int c, int d) {
  return __byte_perm(__byte_perm((uint32_t)a, (uint32_t)b, 0x0040),
                     __byte_perm((uint32_t)c, (uint32_t)d, 0x0040), 0x5410);
}

// ---------------------------------------------------------------------------

__global__ void __launch_bounds__(kThreads, 2)
hqq_mma_kernel(const float* __restrict__ x,
               const int* __restrict__ qw,
               const float* __restrict__ snz,
               const int* __restrict__ tpe,
               float* __restrict__ out) {
  extern __shared__ __align__(1024) char smem[];
  const int tid = threadIdx.x;
  const int wid = tid >> 5;
  const int l   = tid & 31;

  const int e  = blockIdx.z;
  const int nt = blockIdx.x;
  const int mt = blockIdx.y;

  int off = 0, cnt = 0;
#pragma unroll
  for (int i = 0; i < kE; i++) {
    int c = __ldg(&tpe[i]);
    if (i < e) off += c;
    if (i == e) cnt = c;
  }
  if (mt * kBM >= cnt) return;

  const int row0  = off + mt * kBM;
  const int nrows = min(kBM, cnt - mt * kBM);
  const int n0    = nt * kBN;

  const uint32_t sbase = smem_u32(smem);

  // ---- fill mappings ----
  const int a_c4 = l & 15;
  const int a_mr = tid >> 4;
  const int b_npb = (wid & 3) * 16 + (l >> 2);
  const int b_kpb = (wid >> 2) * 16 + (l & 3);

  // ---- warp roles / fragment addressing ----
  const int wk = wid >> 2;                 // k-half owner: ks in {2wk, 2wk+1}
  const int wn = wid & 3;                  // col block 32*wn
  const int rowA0 = l & 15;                // + mi*16, mi 0..3 (rows 0..63)
  const int segA  = l >> 4;
  const int rowBx4 = wn * 32 + ((l >> 4) & 1) * 8 + (l & 7);
  const int segBx4 = (l >> 3) & 1;
  const int rowB0 = wn * 32 + (l & 7);
  const int segB  = (l >> 3) & 1;

  // ---- staging ----
  float4   xv[4];
  uint32_t qpk[8];
  float4   sz4[2];                          // {s,z,s,z} for cols 2np, 2np+1
  float2   szv = make_float2(0.f, 0.f);     // for zp column (tid < 128)

  float mast[64];                           // 64x32 warp tile partial (k-half)
#pragma unroll
  for (int i = 0; i < 64; i++) mast[i] = 0.f;

  auto load_chunk = [&](int ch) {
    const int k0 = ch * kBK;
    const float* xp = x + ((size_t)(row0 + a_mr)) * kIN + k0 + a_c4 * 4;
#pragma unroll
    for (int p = 0; p < 4; p++) {
      const int m = a_mr + p * 16;
      xv[p] = (m < nrows) ? *(const float4*)(xp + (size_t)p * 16 * kIN)
                          : make_float4(0.f, 0.f, 0.f, 0.f);
    }
#pragma unroll
    for (int p = 0; p < 8; p++) {
      const int np = b_npb + 8 * (p & 1);
      const int kk = 2 * (b_kpb + 4 * (p >> 1));
      const int* qb = qw + ((size_t)e * kIN + k0 + kk) * kOUT + n0 + 2 * np;
      const int2 a = *(const int2*)(qb);
      const int2 b = *(const int2*)(qb + kOUT);
      qpk[p] = pack4b(a.x, b.x, a.y, b.y);
    }
#pragma unroll
    for (int j = 0; j < 2; j++) {
      const int np = b_npb + 8 * j;
      sz4[j] = *(const float4*)(snz + (((size_t)e * kG + ch) * kOUT + n0 + 2 * np) * 2);
    }
    if (tid < 128)
      szv = *(const float2*)(snz + (((size_t)e * kG + ch) * kOUT + n0 + tid) * 2);
  };

  auto store_chunk = [&](int buf, int ch) {
    char* st = smem + buf * kStageB;
    // A tile: fp32 -> fp16, SW128; rowsum -> R hi/lo
#pragma unroll
    for (int p = 0; p < 4; p++) {
      const int m = a_mr + p * 16;
      const float4 v = xv[p];
      const uint32_t h0 = pack_f16x2(v.x, v.y);
      const uint32_t h1 = pack_f16x2(v.z, v.w);
      const uint32_t o = sw128((uint32_t)(m * 128 + a_c4 * 8));
      *(uint2*)(st + o) = make_uint2(h0, h1);
      float rs = (v.x + v.y) + (v.z + v.w);
      rs += __shfl_xor_sync(0xffffffffu, rs, 1);
      rs += __shfl_xor_sync(0xffffffffu, rs, 2);
      rs += __shfl_xor_sync(0xffffffffu, rs, 4);
      rs += __shfl_xor_sync(0xffffffffu, rs, 8);
      if ((l & 15) == 0) {
        const __nv_bfloat16 rh = __float2bfloat16(rs);
        const __nv_bfloat16 rl = __float2bfloat16(rs - __bfloat162float(rh));
        *(__nv_bfloat16*)(smem + kRhOff + m * 64 + ch * 2) = rh;
        *(__nv_bfloat16*)(smem + kRlOff + m * 64 + ch * 2) = rl;
      }
    }
    // B tile: w = q * s folded at convert, N-major rows (128B), SW128
#pragma unroll
    for (int p = 0; p < 8; p++) {
      const int np = b_npb + 8 * (p & 1);
      const int kp = b_kpb + 4 * (p >> 1);
      const uint32_t w = qpk[p];
      const float s0 = sz4[p & 1].x;
      const float s1 = sz4[p & 1].z;
      const uint32_t h_r0 =
          pack_f16x2((float)(w & 0xffu) * s0, (float)((w >> 8) & 0xffu) * s0);
      const uint32_t h_r1 =
          pack_f16x2((float)((w >> 16) & 0xffu) * s1, (float)(w >> 24) * s1);
      *(uint32_t*)(st + kATileB + sw128((uint32_t)((2 * np) * 128 + kp * 4)))     = h_r0;
      *(uint32_t*)(st + kATileB + sw128((uint32_t)((2 * np + 1) * 128 + kp * 4))) = h_r1;
    }
    // Z (zp) hi/lo columns for this group
    if (tid < 128) {
      const float s   = szv.x;
      const float zpf = szv.y - 8.f * s;
      const __nv_bfloat16 zh = __float2bfloat16(zpf);
      const __nv_bfloat16 zl = __float2bfloat16(zpf - __bfloat162float(zh));
      *(__nv_bfloat16*)(smem + kZhOff + tid * 64 + ch * 2) = zh;
      *(__nv_bfloat16*)(smem + kZlOff + tid * 64 + ch * 2) = zl;
    }
  };

  // ---- main pipeline: single barrier per chunk, double-buffered ----
  load_chunk(0);
  for (int ch = 0; ch < kNCh; ch++) {
    const int buf = ch & 1;
    store_chunk(buf, ch);
    __syncthreads();
    if (ch + 1 < kNCh) load_chunk(ch + 1);

    const uint32_t base = sbase + buf * kStageB;
#pragma unroll
    for (int ki = 0; ki < 2; ki++) {
      const int ks = wk * 2 + ki;          // this warp's k-quarter
      uint32_t Bf[4][2];
#pragma unroll
      for (int np2 = 0; np2 < 2; np2++) {
        const int row = rowBx4 + np2 * 16;
        const uint32_t o = (uint32_t)(row * 128) +
                           (((uint32_t)(ks * 32 + segBx4 * 16)) ^ ((row & 7) << 4));
        uint32_t r[4];
        ldsm_x4(r, base + kATileB + o);
        Bf[np2 * 2][0]     = r[0];
        Bf[np2 * 2][1]     = r[1];
        Bf[np2 * 2 + 1][0] = r[2];
        Bf[np2 * 2 + 1][1] = r[3];
      }
      // A rows in two halves to bound register liveness
#pragma unroll
      for (int mh = 0; mh < 2; mh++) {
        uint32_t Af[2][4];
#pragma unroll
        for (int mi2 = 0; mi2 < 2; mi2++) {
          const int row = rowA0 + (mh * 2 + mi2) * 16;
          const uint32_t o = (uint32_t)(row * 128) +
                             (((uint32_t)(ks * 32 + segA * 16)) ^ ((row & 7) << 4));
          ldsm_x4(Af[mi2], base + o);
        }
#pragma unroll
        for (int mi2 = 0; mi2 < 2; mi2++)
#pragma unroll
          for (int ni = 0; ni < 4; ni++)
            mma_f16(&mast[((mh * 2 + mi2) * 4 + ni) * 4], Af[mi2],
                    Bf[ni][0], Bf[ni][1]);
      }
    }
    // no second barrier: store(buf) at ch+2 is ordered by the barrier at ch+1
  }

  // ---- combine the two k-halves (scratch overlays stage buffers) ----
  __syncthreads();                       // all MMA reads of stages complete
  {
    // each warp stores its NON-owned row half to scratch[owner][wn]
    char* sc = smem + (((1 - wk) * 4 + wn) * 4096);
    const int rloc = l >> 2;
    const int cloc = (l & 3) * 2;
#pragma unroll
    for (int mi2 = 0; mi2 < 2; mi2++) {
#pragma unroll
      for (int ni = 0; ni < 4; ni++) {
        const float* c = &mast[((2 * (1 - wk) + mi2) * 4 + ni) * 4];
        const int r = mi2 * 16 + rloc;
        const int cc = ni * 8 + cloc;
        *(float2*)(sc + (size_t)((r)     * 32 + cc) * 4) = make_float2(c[0], c[1]);
        *(float2*)(sc + (size_t)((r + 8) * 32 + cc) * 4) = make_float2(c[2], c[3]);
      }
    }
    __syncthreads();
    // add partner's contribution to the OWNED half
    char* so = smem + ((wk * 4 + wn) * 4096);
#pragma unroll
    for (int mi2 = 0; mi2 < 2; mi2++) {
#pragma unroll
      for (int ni = 0; ni < 4; ni++) {
        float* f = &mast[((2 * wk + mi2) * 4 + ni) * 4];
        const int r = mi2 * 16 + rloc;
        const int cc = ni * 8 + cloc;
        const float2 a = *(const float2*)(so + (size_t)((r)     * 32 + cc) * 4);
        const float2 b = *(const float2*)(so + (size_t)((r + 8) * 32 + cc) * 4);
        f[0] += a.x; f[1] += a.y; f[2] += b.x; f[3] += b.y;
      }
    }
  }

  // ---- rank-32 zero-point correction on the owned half (3-term bf16) ----
  {
    const uint32_t Rh = sbase + kRhOff;
    const uint32_t Rl = sbase + kRlOff;
    const uint32_t Zh = sbase + kZhOff;
    const uint32_t Zl = sbase + kZlOff;
    const int rowA0c = wk * 32 + (l & 15);
#pragma unroll
    for (int ks = 0; ks < 2; ks++) {
      uint32_t Arh[2][4], Arl[2][4], Bzh[4][2], Bzl[4][2];
#pragma unroll
      for (int mi2 = 0; mi2 < 2; mi2++) {
        const uint32_t o = (uint32_t)((rowA0c + mi2 * 16) * 64 + ks * 32 + segA * 16);
        ldsm_x4(Arh[mi2], Rh + o);
        ldsm_x4(Arl[mi2], Rl + o);
      }
#pragma unroll
      for (int ni = 0; ni < 4; ni++) {
        const uint32_t o = (uint32_t)((rowB0 + ni * 8) * 64 + ks * 32 + segB * 16);
        ldsm_x2(Bzh[ni], Zh + o);
        ldsm_x2(Bzl[ni], Zl + o);
      }
#pragma unroll
      for (int mi2 = 0; mi2 < 2; mi2++)
#pragma unroll
        for (int ni = 0; ni < 4; ni++) {
          float* c = &mast[((2 * wk + mi2) * 4 + ni) * 4];
          mma_bf16(c, Arh[mi2], Bzh[ni]);
          mma_bf16(c, Arl[mi2], Bzh[ni]);
          mma_bf16(c, Arh[mi2], Bzl[ni]);
        }
    }
  }

  // ---- epilogue: each warp stores its owned 32x32 quadrant ----
#pragma unroll
  for (int mi2 = 0; mi2 < 2; mi2++) {
#pragma unroll
    for (int ni = 0; ni < 4; ni++) {
      const float* c = &mast[((2 * wk + mi2) * 4 + ni) * 4];
      const int r0  = wk * 32 + mi2 * 16 + (l >> 2);
      const int col = n0 + wn * 32 + ni * 8 + (l & 3) * 2;
      if (r0 < nrows)
        *(float2*)(out + (size_t)(row0 + r0) * kOUT + col) = make_float2(c[0], c[1]);
      if (r0 + 8 < nrows)
        *(float2*)(out + (size_t)(row0 + r0 + 8) * kOUT + col) = make_float2(c[2], c[3]);
    }
  }
}

}  // namespace

// ---------------------------------------------------------------------------

extern "C" void kernel_launch(void* const* d_in, const int* in_sizes, int n_in,
                              void* d_out, int out_size) {
  (void)in_sizes; (void)n_in; (void)out_size;
  const float* x   = (const float*)d_in[0];
  const int*   qw  = (const int*)d_in[1];
  const float* snz = (const float*)d_in[2];
  const int*   tpe = (const int*)d_in[3];
  float* out = (float*)d_out;

  (void)cudaFuncSetAttribute(hqq_mma_kernel,
                             cudaFuncAttributeMaxDynamicSharedMemorySize, kSmemB);

  dim3 grid(kOUT / kBN, 2048 / kBM, kE);   // (16, 32, 8); empty m-tiles early-exit
  hqq_mma_kernel<<<grid, kThreads, kSmemB>>>(x, qw, snz, tpe, out);
}

// round 10
// speedup vs baseline: 1.6684x; 1.6684x over previous
#include <cuda_runtime.h>
#include <cuda_bf16.h>
#include <cuda_fp16.h>
#include <cstdint>

// ============================================================================
// HQQ grouped int4 GEMM, sm_103 base target, mma.sync fp16 path.
//
// W = q*s + zp (zp = z - 8s).  Per quant group g (K-chunk of 64):
//   mast  += x_f16 @ (q*s)_f16   (s folded into B at dequant; fp32 accum)
//   out   += R @ Z^T             (rank-32 zero-point correction, bf16 hi/lo)
//
// R10 = R8 shape (CTA 256 thr, tile 64x128, 2 CTAs/SM, warp grid 2x4) with
// fold-s: no P accumulator, no rescale pass, no s SMEM array.
// ============================================================================

namespace {

constexpr int kE   = 8;
constexpr int kIN  = 2048;
constexpr int kOUT = 2048;
constexpr int kG   = 32;

constexpr int kBM  = 64;
constexpr int kBN  = 128;
constexpr int kBK  = 64;                  // == group size
constexpr int kNCh = kIN / kBK;           // 32
constexpr int kThreads = 256;             // 8 warps, 2x4 warp grid

constexpr int kATileB = kBM * kBK * 2;    // 8 KB
constexpr int kBTileB = kBN * kBK * 2;    // 16 KB
constexpr int kStageB = kATileB + kBTileB;           // 24576
constexpr int kRZoff  = 2 * kStageB;                 // 49152
constexpr int kRhOff = kRZoff;                       // R_hi 4KB (64 x 32 bf16)
constexpr int kRlOff = kRZoff + 4096;                // R_lo 4KB
constexpr int kZhOff = kRZoff + 8192;                // Z_hi 8KB (128 x 32)
constexpr int kZlOff = kRZoff + 16384;               // Z_lo 8KB
constexpr int kSmemB = kRZoff + 24576;               // 73728

// ---------------------------------------------------------------------------

__device__ __forceinline__ uint32_t smem_u32(const void* p) {
  uint32_t a;
  asm("{ .reg .u64 t; cvta.to.shared.u64 t, %1; cvt.u32.u64 %0, t; }" : "=r"(a) : "l"(p));
  return a;
}

__device__ __forceinline__ uint32_t pack_f16x2(float lo, float hi) {
  uint32_t r;
  asm("cvt.rn.f16x2.f32 %0, %1, %2;" : "=r"(r) : "f"(hi), "f"(lo));
  return r;
}

__device__ __forceinline__ uint32_t sw128(uint32_t off) {
  return off ^ ((off >> 3) & 0x70);
}

__device__ __forceinline__ void ldsm_x4(uint32_t* r, uint32_t addr) {
  asm volatile("ldmatrix.sync.aligned.m8n8.x4.shared.b16 {%0,%1,%2,%3}, [%4];"
               : "=r"(r[0]), "=r"(r[1]), "=r"(r[2]), "=r"(r[3]) : "r"(addr));
}

__device__ __forceinline__ void ldsm_x2(uint32_t* r, uint32_t addr) {
  asm volatile("ldmatrix.sync.aligned.m8n8.x2.shared.b16 {%0,%1}, [%2];"
               : "=r"(r[0]), "=r"(r[1]) : "r"(addr));
}

__device__ __forceinline__ void mma_f16(float* c, const uint32_t* a,
                                        uint32_t b0, uint32_t b1) {
  asm volatile(
      "mma.sync.aligned.m16n8k16.row.col.f32.f16.f16.f32 "
      "{%0,%1,%2,%3}, {%4,%5,%6,%7}, {%8,%9}, {%0,%1,%2,%3};"
      : "+f"(c[0]), "+f"(c[1]), "+f"(c[2]), "+f"(c[3])
      : "r"(a[0]), "r"(a[1]), "r"(a[2]), "r"(a[3]), "r"(b0), "r"(b1));
}

__device__ __forceinline__ void mma_bf16(float* c, const uint32_t* a, const uint32_t* b) {
  asm volatile(
      "mma.sync.aligned.m16n8k16.row.col.f32.bf16.bf16.f32 "
      "{%0,%1,%2,%3}, {%4,%5,%6,%7}, {%8,%9}, {%0,%1,%2,%3};"
      : "+f"(c[0]), "+f"(c[1]), "+f"(c[2]), "+f"(c[3])
      : "r"(a[0]), "r"(a[1]), "r"(a[2]), "r"(a[3]), "r"(b[0]), "r"(b[1]));
}

__device__ __forceinline__ uint32_t pack4b(int a, int b, int c, int d) {
  return __byte_perm(__byte_perm((uint32_t)a, (uint32_t)b, 0x0040),
                     __byte_perm((uint32_t)c, (uint32_t)d, 0x0040), 0x5410);
}

// ---------------------------------------------------------------------------

__global__ void __launch_bounds__(kThreads, 2)
hqq_mma_kernel(const float* __restrict__ x,
               const int* __restrict__ qw,
               const float* __restrict__ snz,
               const int* __restrict__ tpe,
               float* __restrict__ out) {
  extern __shared__ __align__(1024) char smem[];
  const int tid = threadIdx.x;
  const int wid = tid >> 5;
  const int l   = tid & 31;

  const int e  = blockIdx.z;
  const int nt = blockIdx.x;
  const int mt = blockIdx.y;

  int off = 0, cnt = 0;
#pragma unroll
  for (int i = 0; i < kE; i++) {
    int c = __ldg(&tpe[i]);
    if (i < e) off += c;
    if (i == e) cnt = c;
  }
  if (mt * kBM >= cnt) return;

  const int row0  = off + mt * kBM;
  const int nrows = min(kBM, cnt - mt * kBM);
  const int n0    = nt * kBN;

  const uint32_t sbase = smem_u32(smem);

  // ---- fill mappings ----
  const int a_c4 = l & 15;
  const int a_mr = tid >> 4;
  const int b_npb = (wid & 3) * 16 + (l >> 2);
  const int b_kpb = (wid >> 2) * 16 + (l & 3);

  // ---- mma fragment addressing (warp grid 2x4, warp tile 32x32) ----
  const int wm = wid >> 2;                 // 0..1
  const int wn = wid & 3;                  // 0..3
  const int rowA0 = wm * 32 + (l & 15);
  const int segA  = l >> 4;
  const int rowBx4 = wn * 32 + ((l >> 4) & 1) * 8 + (l & 7);
  const int segBx4 = (l >> 3) & 1;
  const int rowB0 = wn * 32 + (l & 7);
  const int segB  = (l >> 3) & 1;

  // ---- staging ----
  float4   xv[4];
  uint32_t qpk[8];
  float4   sz4[2];                          // {s,z,s,z} for cols 2np, 2np+1
  float2   szv = make_float2(0.f, 0.f);     // zp column source (tid < 128)

  float mast[32];
#pragma unroll
  for (int i = 0; i < 32; i++) mast[i] = 0.f;

  auto load_chunk = [&](int ch) {
    const int k0 = ch * kBK;
    const float* xp = x + ((size_t)(row0 + a_mr)) * kIN + k0 + a_c4 * 4;
#pragma unroll
    for (int p = 0; p < 4; p++) {
      const int m = a_mr + p * 16;
      xv[p] = (m < nrows) ? *(const float4*)(xp + (size_t)p * 16 * kIN)
                          : make_float4(0.f, 0.f, 0.f, 0.f);
    }
#pragma unroll
    for (int p = 0; p < 8; p++) {
      const int np = b_npb + 8 * (p & 1);
      const int kk = 2 * (b_kpb + 4 * (p >> 1));
      const int* qb = qw + ((size_t)e * kIN + k0 + kk) * kOUT + n0 + 2 * np;
      const int2 a = *(const int2*)(qb);
      const int2 b = *(const int2*)(qb + kOUT);
      qpk[p] = pack4b(a.x, b.x, a.y, b.y);
    }
#pragma unroll
    for (int j = 0; j < 2; j++) {
      const int np = b_npb + 8 * j;
      sz4[j] = *(const float4*)(snz + (((size_t)e * kG + ch) * kOUT + n0 + 2 * np) * 2);
    }
    if (tid < 128)
      szv = *(const float2*)(snz + (((size_t)e * kG + ch) * kOUT + n0 + tid) * 2);
  };

  auto store_chunk = [&](int buf, int ch) {
    char* st = smem + buf * kStageB;
    // A tile: fp32 -> fp16, SW128; rowsum -> R hi/lo
#pragma unroll
    for (int p = 0; p < 4; p++) {
      const int m = a_mr + p * 16;
      const float4 v = xv[p];
      const uint32_t h0 = pack_f16x2(v.x, v.y);
      const uint32_t h1 = pack_f16x2(v.z, v.w);
      const uint32_t o = sw128((uint32_t)(m * 128 + a_c4 * 8));
      *(uint2*)(st + o) = make_uint2(h0, h1);
      float rs = (v.x + v.y) + (v.z + v.w);
      rs += __shfl_xor_sync(0xffffffffu, rs, 1);
      rs += __shfl_xor_sync(0xffffffffu, rs, 2);
      rs += __shfl_xor_sync(0xffffffffu, rs, 4);
      rs += __shfl_xor_sync(0xffffffffu, rs, 8);
      if ((l & 15) == 0) {
        const __nv_bfloat16 rh = __float2bfloat16(rs);
        const __nv_bfloat16 rl = __float2bfloat16(rs - __bfloat162float(rh));
        *(__nv_bfloat16*)(smem + kRhOff + m * 64 + ch * 2) = rh;
        *(__nv_bfloat16*)(smem + kRlOff + m * 64 + ch * 2) = rl;
      }
    }
    // B tile: w = q * s folded at convert (single fp16 rounding), SW128
#pragma unroll
    for (int p = 0; p < 8; p++) {
      const int np = b_npb + 8 * (p & 1);
      const int kp = b_kpb + 4 * (p >> 1);
      const uint32_t w = qpk[p];
      const float s0 = sz4[p & 1].x;
      const float s1 = sz4[p & 1].z;
      const uint32_t h_r0 =
          pack_f16x2((float)(w & 0xffu) * s0, (float)((w >> 8) & 0xffu) * s0);
      const uint32_t h_r1 =
          pack_f16x2((float)((w >> 16) & 0xffu) * s1, (float)(w >> 24) * s1);
      *(uint32_t*)(st + kATileB + sw128((uint32_t)((2 * np) * 128 + kp * 4)))     = h_r0;
      *(uint32_t*)(st + kATileB + sw128((uint32_t)((2 * np + 1) * 128 + kp * 4))) = h_r1;
    }
    // Z (zp) hi/lo columns for this group
    if (tid < 128) {
      const float s   = szv.x;
      const float zpf = szv.y - 8.f * s;
      const __nv_bfloat16 zh = __float2bfloat16(zpf);
      const __nv_bfloat16 zl = __float2bfloat16(zpf - __bfloat162float(zh));
      *(__nv_bfloat16*)(smem + kZhOff + tid * 64 + ch * 2) = zh;
      *(__nv_bfloat16*)(smem + kZlOff + tid * 64 + ch * 2) = zl;
    }
  };

  // ---- main pipeline: single barrier per chunk, double-buffered ----
  load_chunk(0);
  for (int ch = 0; ch < kNCh; ch++) {
    const int buf = ch & 1;
    store_chunk(buf, ch);
    __syncthreads();
    if (ch + 1 < kNCh) load_chunk(ch + 1);

    const uint32_t base = sbase + buf * kStageB;
#pragma unroll
    for (int ks = 0; ks < 4; ks++) {
      uint32_t Af[2][4], Bf[4][2];
#pragma unroll
      for (int mi = 0; mi < 2; mi++) {
        const int row = rowA0 + mi * 16;
        const uint32_t o = (uint32_t)(row * 128) +
                           (((uint32_t)(ks * 32 + segA * 16)) ^ ((row & 7) << 4));
        ldsm_x4(Af[mi], base + o);
      }
#pragma unroll
      for (int np = 0; np < 2; np++) {
        const int row = rowBx4 + np * 16;
        const uint32_t o = (uint32_t)(row * 128) +
                           (((uint32_t)(ks * 32 + segBx4 * 16)) ^ ((row & 7) << 4));
        uint32_t r[4];
        ldsm_x4(r, base + kATileB + o);
        Bf[np * 2][0]     = r[0];
        Bf[np * 2][1]     = r[1];
        Bf[np * 2 + 1][0] = r[2];
        Bf[np * 2 + 1][1] = r[3];
      }
#pragma unroll
      for (int mi = 0; mi < 2; mi++)
#pragma unroll
        for (int ni = 0; ni < 4; ni++)
          mma_f16(&mast[(mi * 4 + ni) * 4], Af[mi], Bf[ni][0], Bf[ni][1]);
    }
    // no second barrier: store(buf) at ch+2 is ordered by the barrier at ch+1
  }

  // ---- rank-32 zero-point correction: mast += R @ Z^T (3-term bf16 hi/lo) ----
  {
    const uint32_t Rh = sbase + kRhOff;
    const uint32_t Rl = sbase + kRlOff;
    const uint32_t Zh = sbase + kZhOff;
    const uint32_t Zl = sbase + kZlOff;
#pragma unroll
    for (int ks = 0; ks < 2; ks++) {
      uint32_t Arh[2][4], Arl[2][4], Bzh[4][2], Bzl[4][2];
#pragma unroll
      for (int mi = 0; mi < 2; mi++) {
        const uint32_t o = (uint32_t)((rowA0 + mi * 16) * 64 + ks * 32 + segA * 16);
        ldsm_x4(Arh[mi], Rh + o);
        ldsm_x4(Arl[mi], Rl + o);
      }
#pragma unroll
      for (int ni = 0; ni < 4; ni++) {
        const uint32_t o = (uint32_t)((rowB0 + ni * 8) * 64 + ks * 32 + segB * 16);
        ldsm_x2(Bzh[ni], Zh + o);
        ldsm_x2(Bzl[ni], Zl + o);
      }
#pragma unroll
      for (int mi = 0; mi < 2; mi++)
#pragma unroll
        for (int ni = 0; ni < 4; ni++) {
          float* c = &mast[(mi * 4 + ni) * 4];
          mma_bf16(c, Arh[mi], Bzh[ni]);
          mma_bf16(c, Arl[mi], Bzh[ni]);
          mma_bf16(c, Arh[mi], Bzl[ni]);
        }
    }
  }

  // ---- epilogue ----
#pragma unroll
  for (int mi = 0; mi < 2; mi++) {
#pragma unroll
    for (int ni = 0; ni < 4; ni++) {
      const float* c = &mast[(mi * 4 + ni) * 4];
      const int r0  = wm * 32 + mi * 16 + (l >> 2);
      const int col = n0 + wn * 32 + ni * 8 + (l & 3) * 2;
      if (r0 < nrows)
        *(float2*)(out + (size_t)(row0 + r0) * kOUT + col) = make_float2(c[0], c[1]);
      if (r0 + 8 < nrows)
        *(float2*)(out + (size_t)(row0 + r0 + 8) * kOUT + col) = make_float2(c[2], c[3]);
    }
  }
}

}  // namespace

// ---------------------------------------------------------------------------

extern "C" void kernel_launch(void* const* d_in, const int* in_sizes, int n_in,
                              void* d_out, int out_size) {
  (void)in_sizes; (void)n_in; (void)out_size;
  const float* x   = (const float*)d_in[0];
  const int*   qw  = (const int*)d_in[1];
  const float* snz = (const float*)d_in[2];
  const int*   tpe = (const int*)d_in[3];
  float* out = (float*)d_out;

  (void)cudaFuncSetAttribute(hqq_mma_kernel,
                             cudaFuncAttributeMaxDynamicSharedMemorySize, kSmemB);

  dim3 grid(kOUT / kBN, 2048 / kBM, kE);   // (16, 32, 8); empty m-tiles early-exit
  hqq_mma_kernel<<<grid, kThreads, kSmemB>>>(x, qw, snz, tpe, out);
}

// round 11
// speedup vs baseline: 1.9042x; 1.1413x over previous
#include <cuda_runtime.h>
#include <cuda_bf16.h>
#include <cuda_fp16.h>
#include <cstdint>

// ============================================================================
// HQQ grouped int4 GEMM, sm_103 base target, mma.sync fp16 path.
//
// Full fold: W = q*s + (z - 8s), computed in fp32 and rounded ONCE to fp16
// at dequant. Single GEMM, no correction pass:
//   mast += x_f16 @ W_f16      (fp32 accumulate)
//
// R11 = R10 shape (CTA 256 thr, tile 64x128, 2 CTAs/SM, warp grid 2x4) minus
// the rank-32 zero-point machinery (rowsum shfls, R/Z tiles, tail MMAs).
// ============================================================================

namespace {

constexpr int kE   = 8;
constexpr int kIN  = 2048;
constexpr int kOUT = 2048;
constexpr int kG   = 32;

constexpr int kBM  = 64;
constexpr int kBN  = 128;
constexpr int kBK  = 64;                  // == quant group size
constexpr int kNCh = kIN / kBK;           // 32
constexpr int kThreads = 256;             // 8 warps, 2x4 warp grid

constexpr int kATileB = kBM * kBK * 2;    // 8 KB
constexpr int kBTileB = kBN * kBK * 2;    // 16 KB
constexpr int kStageB = kATileB + kBTileB;           // 24576
constexpr int kSmemB  = 2 * kStageB;                 // 49152

// ---------------------------------------------------------------------------

__device__ __forceinline__ uint32_t smem_u32(const void* p) {
  uint32_t a;
  asm("{ .reg .u64 t; cvta.to.shared.u64 t, %1; cvt.u32.u64 %0, t; }" : "=r"(a) : "l"(p));
  return a;
}

__device__ __forceinline__ uint32_t pack_f16x2(float lo, float hi) {
  uint32_t r;
  asm("cvt.rn.f16x2.f32 %0, %1, %2;" : "=r"(r) : "f"(hi), "f"(lo));
  return r;
}

__device__ __forceinline__ uint32_t sw128(uint32_t off) {
  return off ^ ((off >> 3) & 0x70);
}

__device__ __forceinline__ void ldsm_x4(uint32_t* r, uint32_t addr) {
  asm volatile("ldmatrix.sync.aligned.m8n8.x4.shared.b16 {%0,%1,%2,%3}, [%4];"
               : "=r"(r[0]), "=r"(r[1]), "=r"(r[2]), "=r"(r[3]) : "r"(addr));
}

__device__ __forceinline__ void mma_f16(float* c, const uint32_t* a,
                                        uint32_t b0, uint32_t b1) {
  asm volatile(
      "mma.sync.aligned.m16n8k16.row.col.f32.f16.f16.f32 "
      "{%0,%1,%2,%3}, {%4,%5,%6,%7}, {%8,%9}, {%0,%1,%2,%3};"
      : "+f"(c[0]), "+f"(c[1]), "+f"(c[2]), "+f"(c[3])
      : "r"(a[0]), "r"(a[1]), "r"(a[2]), "r"(a[3]), "r"(b0), "r"(b1));
}

__device__ __forceinline__ uint32_t pack4b(int a, int b, int c, int d) {
  return __byte_perm(__byte_perm((uint32_t)a, (uint32_t)b, 0x0040),
                     __byte_perm((uint32_t)c, (uint32_t)d, 0x0040), 0x5410);
}

// ---------------------------------------------------------------------------

__global__ void __launch_bounds__(kThreads, 2)
hqq_mma_kernel(const float* __restrict__ x,
               const int* __restrict__ qw,
               const float* __restrict__ snz,
               const int* __restrict__ tpe,
               float* __restrict__ out) {
  extern __shared__ __align__(1024) char smem[];
  const int tid = threadIdx.x;
  const int wid = tid >> 5;
  const int l   = tid & 31;

  const int e  = blockIdx.z;
  const int nt = blockIdx.x;
  const int mt = blockIdx.y;

  int off = 0, cnt = 0;
#pragma unroll
  for (int i = 0; i < kE; i++) {
    int c = __ldg(&tpe[i]);
    if (i < e) off += c;
    if (i == e) cnt = c;
  }
  if (mt * kBM >= cnt) return;

  const int row0  = off + mt * kBM;
  const int nrows = min(kBM, cnt - mt * kBM);
  const int n0    = nt * kBN;

  const uint32_t sbase = smem_u32(smem);

  // ---- fill mappings ----
  const int a_c4 = l & 15;
  const int a_mr = tid >> 4;
  const int b_npb = (wid & 3) * 16 + (l >> 2);
  const int b_kpb = (wid >> 2) * 16 + (l & 3);

  // ---- mma fragment addressing (warp grid 2x4, warp tile 32x32) ----
  const int wm = wid >> 2;                 // 0..1
  const int wn = wid & 3;                  // 0..3
  const int rowA0 = wm * 32 + (l & 15);
  const int segA  = l >> 4;
  const int rowBx4 = wn * 32 + ((l >> 4) & 1) * 8 + (l & 7);
  const int segBx4 = (l >> 3) & 1;

  // ---- staging ----
  float4   xv[4];
  uint32_t qpk[8];
  float4   sz4[2];                          // {s,z,s,z} for cols 2np, 2np+1

  float mast[32];
#pragma unroll
  for (int i = 0; i < 32; i++) mast[i] = 0.f;

  auto load_chunk = [&](int ch) {
    const int k0 = ch * kBK;
    const float* xp = x + ((size_t)(row0 + a_mr)) * kIN + k0 + a_c4 * 4;
#pragma unroll
    for (int p = 0; p < 4; p++) {
      const int m = a_mr + p * 16;
      xv[p] = (m < nrows) ? *(const float4*)(xp + (size_t)p * 16 * kIN)
                          : make_float4(0.f, 0.f, 0.f, 0.f);
    }
#pragma unroll
    for (int p = 0; p < 8; p++) {
      const int np = b_npb + 8 * (p & 1);
      const int kk = 2 * (b_kpb + 4 * (p >> 1));
      const int* qb = qw + ((size_t)e * kIN + k0 + kk) * kOUT + n0 + 2 * np;
      const int2 a = *(const int2*)(qb);
      const int2 b = *(const int2*)(qb + kOUT);
      qpk[p] = pack4b(a.x, b.x, a.y, b.y);
    }
#pragma unroll
    for (int j = 0; j < 2; j++) {
      const int np = b_npb + 8 * j;
      sz4[j] = *(const float4*)(snz + (((size_t)e * kG + ch) * kOUT + n0 + 2 * np) * 2);
    }
  };

  auto store_chunk = [&](int buf) {
    char* st = smem + buf * kStageB;
    // A tile: fp32 -> fp16, SW128 (rows of 128B)
#pragma unroll
    for (int p = 0; p < 4; p++) {
      const int m = a_mr + p * 16;
      const float4 v = xv[p];
      const uint32_t h0 = pack_f16x2(v.x, v.y);
      const uint32_t h1 = pack_f16x2(v.z, v.w);
      const uint32_t o = sw128((uint32_t)(m * 128 + a_c4 * 8));
      *(uint2*)(st + o) = make_uint2(h0, h1);
    }
    // B tile: W = q*s + (z-8s), single fp16 rounding, N-major rows, SW128
    // qpk bytes = {q[k][n], q[k+1][n], q[k][n+1], q[k+1][n+1]}, n = 2*np
#pragma unroll
    for (int p = 0; p < 8; p++) {
      const int np = b_npb + 8 * (p & 1);
      const int kp = b_kpb + 4 * (p >> 1);
      const uint32_t w = qpk[p];
      const float4 sz = sz4[p & 1];
      const float s0 = sz.x, zp0 = fmaf(-8.f, sz.x, sz.y);
      const float s1 = sz.z, zp1 = fmaf(-8.f, sz.z, sz.w);
      const uint32_t h_r0 = pack_f16x2(fmaf((float)(w & 0xffu), s0, zp0),
                                       fmaf((float)((w >> 8) & 0xffu), s0, zp0));
      const uint32_t h_r1 = pack_f16x2(fmaf((float)((w >> 16) & 0xffu), s1, zp1),
                                       fmaf((float)(w >> 24), s1, zp1));
      *(uint32_t*)(st + kATileB + sw128((uint32_t)((2 * np) * 128 + kp * 4)))     = h_r0;
      *(uint32_t*)(st + kATileB + sw128((uint32_t)((2 * np + 1) * 128 + kp * 4))) = h_r1;
    }
  };

  // ---- main pipeline: single barrier per chunk, double-buffered ----
  load_chunk(0);
  for (int ch = 0; ch < kNCh; ch++) {
    const int buf = ch & 1;
    store_chunk(buf);
    __syncthreads();
    if (ch + 1 < kNCh) load_chunk(ch + 1);

    const uint32_t base = sbase + buf * kStageB;
#pragma unroll
    for (int ks = 0; ks < 4; ks++) {
      uint32_t Af[2][4], Bf[4][2];
#pragma unroll
      for (int mi = 0; mi < 2; mi++) {
        const int row = rowA0 + mi * 16;
        const uint32_t o = (uint32_t)(row * 128) +
                           (((uint32_t)(ks * 32 + segA * 16)) ^ ((row & 7) << 4));
        ldsm_x4(Af[mi], base + o);
      }
#pragma unroll
      for (int np = 0; np < 2; np++) {
        const int row = rowBx4 + np * 16;
        const uint32_t o = (uint32_t)(row * 128) +
                           (((uint32_t)(ks * 32 + segBx4 * 16)) ^ ((row & 7) << 4));
        uint32_t r[4];
        ldsm_x4(r, base + kATileB + o);
        Bf[np * 2][0]     = r[0];
        Bf[np * 2][1]     = r[1];
        Bf[np * 2 + 1][0] = r[2];
        Bf[np * 2 + 1][1] = r[3];
      }
#pragma unroll
      for (int mi = 0; mi < 2; mi++)
#pragma unroll
        for (int ni = 0; ni < 4; ni++)
          mma_f16(&mast[(mi * 4 + ni) * 4], Af[mi], Bf[ni][0], Bf[ni][1]);
    }
    // no second barrier: store(buf) at ch+2 is ordered by the barrier at ch+1
  }

  // ---- epilogue ----
#pragma unroll
  for (int mi = 0; mi < 2; mi++) {
#pragma unroll
    for (int ni = 0; ni < 4; ni++) {
      const float* c = &mast[(mi * 4 + ni) * 4];
      const int r0  = wm * 32 + mi * 16 + (l >> 2);
      const int col = n0 + wn * 32 + ni * 8 + (l & 3) * 2;
      if (r0 < nrows)
        *(float2*)(out + (size_t)(row0 + r0) * kOUT + col) = make_float2(c[0], c[1]);
      if (r0 + 8 < nrows)
        *(float2*)(out + (size_t)(row0 + r0 + 8) * kOUT + col) = make_float2(c[2], c[3]);
    }
  }
}

}  // namespace

// ---------------------------------------------------------------------------

extern "C" void kernel_launch(void* const* d_in, const int* in_sizes, int n_in,
                              void* d_out, int out_size) {
  (void)in_sizes; (void)n_in; (void)out_size;
  const float* x   = (const float*)d_in[0];
  const int*   qw  = (const int*)d_in[1];
  const float* snz = (const float*)d_in[2];
  const int*   tpe = (const int*)d_in[3];
  float* out = (float*)d_out;

  (void)cudaFuncSetAttribute(hqq_mma_kernel,
                             cudaFuncAttributeMaxDynamicSharedMemorySize, kSmemB);

  dim3 grid(kOUT / kBN, 2048 / kBM, kE);   // (16, 32, 8); empty m-tiles early-exit
  hqq_mma_kernel<<<grid, kThreads, kSmemB>>>(x, qw, snz, tpe, out);
}

// round 12
// speedup vs baseline: 2.4552x; 1.2894x over previous
#include <cuda_runtime.h>
#include <cuda_fp16.h>
#include <cstdint>

// ============================================================================
// HQQ grouped int4 GEMM, sm_103 base target.
//
// R12: three-kernel plan (one graph):
//   1. convert_x:  xh = fp16(x)                     [2048 x 2048]
//   2. dequantT :  WT[e][n][k] = fp16(q*s + z - 8s) (transposed, n-major)
//   3. main GEMM:  out = xh @ W  per expert slice; cp.async tiles, 64x256 CTA
//      tile, 32x64 warp tiles (64-reg fp32 acc), fragments identical to R11.
// ============================================================================

namespace {

constexpr int kE   = 8;
constexpr int kT   = 2048;
constexpr int kIN  = 2048;
constexpr int kOUT = 2048;
constexpr int kG   = 32;

constexpr int kBM  = 64;
constexpr int kBN  = 256;
constexpr int kBK  = 64;
constexpr int kNCh = kIN / kBK;           // 32
constexpr int kThreads = 256;             // 8 warps, grid 2(m) x 4(n)

constexpr int kATileB = kBM * kBK * 2;    // 8 KB
constexpr int kBTileB = kBN * kBK * 2;    // 32 KB
constexpr int kStageB = kATileB + kBTileB;          // 40960
constexpr int kSmemB  = 2 * kStageB;                // 81920

// static scratch (allocation-free): fp16 x and transposed dequantized W
__device__ __half g_xh[(size_t)kT * kIN];
__device__ __half g_WT[(size_t)kE * kOUT * kIN];

// ---------------------------------------------------------------------------

__device__ __forceinline__ uint32_t smem_u32(const void* p) {
  uint32_t a;
  asm("{ .reg .u64 t; cvta.to.shared.u64 t, %1; cvt.u32.u64 %0, t; }" : "=r"(a) : "l"(p));
  return a;
}

__device__ __forceinline__ uint32_t pack_f16x2(float lo, float hi) {
  uint32_t r;
  asm("cvt.rn.f16x2.f32 %0, %1, %2;" : "=r"(r) : "f"(hi), "f"(lo));
  return r;
}

__device__ __forceinline__ uint32_t sw128(uint32_t off) {
  return off ^ ((off >> 3) & 0x70);
}

__device__ __forceinline__ void ldsm_x4(uint32_t* r, uint32_t addr) {
  asm volatile("ldmatrix.sync.aligned.m8n8.x4.shared.b16 {%0,%1,%2,%3}, [%4];"
               : "=r"(r[0]), "=r"(r[1]), "=r"(r[2]), "=r"(r[3]) : "r"(addr));
}

__device__ __forceinline__ void mma_f16(float* c, const uint32_t* a,
                                        uint32_t b0, uint32_t b1) {
  asm volatile(
      "mma.sync.aligned.m16n8k16.row.col.f32.f16.f16.f32 "
      "{%0,%1,%2,%3}, {%4,%5,%6,%7}, {%8,%9}, {%0,%1,%2,%3};"
      : "+f"(c[0]), "+f"(c[1]), "+f"(c[2]), "+f"(c[3])
      : "r"(a[0]), "r"(a[1]), "r"(a[2]), "r"(a[3]), "r"(b0), "r"(b1));
}

__device__ __forceinline__ void cp16(uint32_t smem_addr, const void* gmem,
                                     uint32_t src_bytes) {
  asm volatile("cp.async.cg.shared.global [%0], [%1], 16, %2;"
               :: "r"(smem_addr), "l"(gmem), "r"(src_bytes) : "memory");
}

#define CP_COMMIT() asm volatile("cp.async.commit_group;" ::: "memory")
#define CP_WAIT0()  asm volatile("cp.async.wait_group 0;" ::: "memory")

// ---------------------------------------------------------------------------
// Kernel 1: x -> fp16
// ---------------------------------------------------------------------------

__global__ void __launch_bounds__(256) convert_x_kernel(const float* __restrict__ x) {
  const size_t g = (size_t)blockIdx.x * 256 + threadIdx.x;   // 1M threads, x4 vec
  const float4 v = *(const float4*)(x + g * 4);
  uint2 o;
  o.x = pack_f16x2(v.x, v.y);
  o.y = pack_f16x2(v.z, v.w);
  *(uint2*)(&g_xh[g * 4]) = o;
}

// ---------------------------------------------------------------------------
// Kernel 2: dequant + transpose.  WT[e][n][k] = fp16(q[e][k][n]*s + (z-8s))
// block: 256 thr, tile 64k x 64n; grid (32 kt, 32 ntile, 8 e)
// ---------------------------------------------------------------------------

__global__ void __launch_bounds__(256)
dequantT_kernel(const int* __restrict__ qw, const float* __restrict__ snz) {
  __shared__ float s_s[64], s_zp[64];
  __shared__ __half s_t[64][64];           // [n][k]

  const int tid = threadIdx.x;
  const int kt = blockIdx.x, ntile = blockIdx.y, e = blockIdx.z;
  const int k0 = kt * 64, n0 = ntile * 64;

  if (tid < 64) {
    const float2 sz = *(const float2*)(snz + (((size_t)e * kG + kt) * kOUT + n0 + tid) * 2);
    s_s[tid]  = sz.x;
    s_zp[tid] = fmaf(-8.f, sz.x, sz.y);
  }
  __syncthreads();

#pragma unroll
  for (int i = 0; i < 4; i++) {
    const int idx = i * 256 + tid;         // 1024 int4 segs
    const int k = idx >> 4;                // 0..63
    const int n = (idx & 15) * 4;          // 0..60
    const int4 q = *(const int4*)(qw + ((size_t)e * kIN + k0 + k) * kOUT + n0 + n);
    s_t[n][k]     = __float2half(fmaf((float)q.x, s_s[n],     s_zp[n]));
    s_t[n + 1][k] = __float2half(fmaf((float)q.y, s_s[n + 1], s_zp[n + 1]));
    s_t[n + 2][k] = __float2half(fmaf((float)q.z, s_s[n + 2], s_zp[n + 2]));
    s_t[n + 3][k] = __float2half(fmaf((float)q.w, s_s[n + 3], s_zp[n + 3]));
  }
  __syncthreads();

#pragma unroll
  for (int i = 0; i < 2; i++) {
    const int idx = i * 256 + tid;         // 512 16B segs
    const int n = idx >> 3;
    const int ks = (idx & 7) * 8;
    *(uint4*)(&g_WT[((size_t)e * kOUT + n0 + n) * kIN + k0 + ks]) =
        *(const uint4*)(&s_t[n][ks]);
  }
}

// ---------------------------------------------------------------------------
// Kernel 3: main GEMM
// ---------------------------------------------------------------------------

__global__ void __launch_bounds__(kThreads, 2)
hqq_mma_kernel(const int* __restrict__ tpe, float* __restrict__ out) {
  extern __shared__ __align__(1024) char smem[];
  const int tid = threadIdx.x;
  const int wid = tid >> 5;
  const int l   = tid & 31;

  const int e  = blockIdx.z;
  const int nt = blockIdx.x;
  const int mt = blockIdx.y;

  int off = 0, cnt = 0;
#pragma unroll
  for (int i = 0; i < kE; i++) {
    int c = __ldg(&tpe[i]);
    if (i < e) off += c;
    if (i == e) cnt = c;
  }
  if (mt * kBM >= cnt) return;

  const int row0  = off + mt * kBM;
  const int nrows = min(kBM, cnt - mt * kBM);
  const int n0    = nt * kBN;

  const uint32_t sbase = smem_u32(smem);

  // ---- mma fragment addressing (warp grid 2x4, warp tile 32x64) ----
  const int wm = wid >> 2;                 // 0..1
  const int wn = wid & 3;                  // 0..3
  const int rowA0 = wm * 32 + (l & 15);
  const int segA  = l >> 4;
  const int rowBo = ((l >> 4) & 1) * 8 + (l & 7);   // + wn*64 + ni2*16
  const int segB  = (l >> 3) & 1;

  // ---- cp.async segment mapping (per thread) ----
  // A: 512 segs: g = i*256+tid, i<2: m = g>>3, kseg = g&7
  // B: 2048 segs: g = i*256+tid, i<8: n = g>>3, kseg = g&7
  const __half* xh_base = &g_xh[0];
  const __half* wt_base = &g_WT[(size_t)e * kOUT * kIN];

  auto issue_stage = [&](int ch, int buf) {
    const int k0 = ch * kBK;
    const uint32_t st = sbase + buf * kStageB;
#pragma unroll
    for (int i = 0; i < 2; i++) {
      const int g = i * 256 + tid;
      const int m = g >> 3, kseg = g & 7;
      cp16(st + sw128((uint32_t)(m * 128 + kseg * 16)),
           xh_base + (size_t)(row0 + m) * kIN + k0 + kseg * 8,
           (m < nrows) ? 16u : 0u);
    }
    const uint32_t stB = st + kATileB;
#pragma unroll
    for (int i = 0; i < 8; i++) {
      const int g = i * 256 + tid;
      const int n = g >> 3, kseg = g & 7;
      cp16(stB + sw128((uint32_t)(n * 128 + kseg * 16)),
           wt_base + (size_t)(n0 + n) * kIN + k0 + kseg * 8, 16u);
    }
    CP_COMMIT();
  };

  float mast[64];
#pragma unroll
  for (int i = 0; i < 64; i++) mast[i] = 0.f;

  issue_stage(0, 0);

  for (int ch = 0; ch < kNCh; ch++) {
    const int buf = ch & 1;
    CP_WAIT0();            // stage(ch) landed (issued by this thread)
    __syncthreads();       // visible to all; mma(ch-1) done everywhere
    if (ch + 1 < kNCh) issue_stage(ch + 1, buf ^ 1);

    const uint32_t base  = sbase + buf * kStageB;
    const uint32_t baseB = base + kATileB;
#pragma unroll
    for (int ks = 0; ks < 4; ks++) {
      uint32_t Af[2][4];
#pragma unroll
      for (int mi = 0; mi < 2; mi++) {
        const int row = rowA0 + mi * 16;
        ldsm_x4(Af[mi], base + (uint32_t)(row * 128) +
                         (((uint32_t)(ks * 32 + segA * 16)) ^ ((row & 7) << 4)));
      }
#pragma unroll
      for (int ni2 = 0; ni2 < 4; ni2++) {
        const int row = wn * 64 + ni2 * 16 + rowBo;
        uint32_t r[4];
        ldsm_x4(r, baseB + (uint32_t)(row * 128) +
                    (((uint32_t)(ks * 32 + segB * 16)) ^ ((row & 7) << 4)));
#pragma unroll
        for (int mi = 0; mi < 2; mi++) {
          mma_f16(&mast[(mi * 8 + ni2 * 2) * 4],     Af[mi], r[0], r[1]);
          mma_f16(&mast[(mi * 8 + ni2 * 2 + 1) * 4], Af[mi], r[2], r[3]);
        }
      }
    }
  }

  // ---- epilogue ----
#pragma unroll
  for (int mi = 0; mi < 2; mi++) {
#pragma unroll
    for (int ni = 0; ni < 8; ni++) {
      const float* c = &mast[(mi * 8 + ni) * 4];
      const int r0  = wm * 32 + mi * 16 + (l >> 2);
      const int col = n0 + wn * 64 + ni * 8 + (l & 3) * 2;
      if (r0 < nrows)
        *(float2*)(out + (size_t)(row0 + r0) * kOUT + col) = make_float2(c[0], c[1]);
      if (r0 + 8 < nrows)
        *(float2*)(out + (size_t)(row0 + r0 + 8) * kOUT + col) = make_float2(c[2], c[3]);
    }
  }
}

}  // namespace

// ---------------------------------------------------------------------------

extern "C" void kernel_launch(void* const* d_in, const int* in_sizes, int n_in,
                              void* d_out, int out_size) {
  (void)in_sizes; (void)n_in; (void)out_size;
  const float* x   = (const float*)d_in[0];
  const int*   qw  = (const int*)d_in[1];
  const float* snz = (const float*)d_in[2];
  const int*   tpe = (const int*)d_in[3];
  float* out = (float*)d_out;

  (void)cudaFuncSetAttribute(hqq_mma_kernel,
                             cudaFuncAttributeMaxDynamicSharedMemorySize, kSmemB);

  convert_x_kernel<<<(kT * kIN) / (256 * 4), 256>>>(x);
  dequantT_kernel<<<dim3(kIN / 64, kOUT / 64, kE), 256>>>(qw, snz);
  dim3 grid(kOUT / kBN, kT / kBM, kE);   // (8, 32, 8); empty m-tiles early-exit
  hqq_mma_kernel<<<grid, kThreads, kSmemB>>>(tpe, out);
}

// round 13
// speedup vs baseline: 3.5605x; 1.4502x over previous
#include <cuda_runtime.h>
#include <cuda_fp16.h>
#include <cstdint>

// ============================================================================
// HQQ grouped int4 GEMM, sm_103 base target.
//
// R13: three-kernel graph, W kept K-MAJOR (no transpose anywhere):
//   1. convert_x: xh = fp16(x)                          [T x IN]
//   2. dequant  : W[e][k][n] = fp16(q*s + z - 8s)       pure streaming, no smem
//   3. main GEMM: 64x256 CTA tile, 32x64 warp tiles, cp.async 2-stage;
//      A via normal ldsm (k-major rows), B via ldmatrix.trans on k-major rows.
// ============================================================================

namespace {

constexpr int kE   = 8;
constexpr int kT   = 2048;
constexpr int kIN  = 2048;
constexpr int kOUT = 2048;
constexpr int kG   = 32;

constexpr int kBM  = 64;
constexpr int kBN  = 256;
constexpr int kBK  = 64;
constexpr int kNCh = kIN / kBK;           // 32
constexpr int kThreads = 256;             // 8 warps, grid 2(m) x 4(n)

constexpr int kATileB = kBM * kBK * 2;    // 8 KB   (rows m, 128B of k)
constexpr int kBRowB  = kBN * 2;          // 512B per k-row
constexpr int kBTileB = kBK * kBRowB;     // 32 KB  (rows k, 512B of n)
constexpr int kStageB = kATileB + kBTileB;          // 40960
constexpr int kSmemB  = 2 * kStageB;                // 81920

__device__ __half g_xh[(size_t)kT * kIN];
__device__ __half g_W[(size_t)kE * kIN * kOUT];     // k-major, same layout as q

// ---------------------------------------------------------------------------

__device__ __forceinline__ uint32_t smem_u32(const void* p) {
  uint32_t a;
  asm("{ .reg .u64 t; cvta.to.shared.u64 t, %1; cvt.u32.u64 %0, t; }" : "=r"(a) : "l"(p));
  return a;
}

__device__ __forceinline__ uint32_t pack_f16x2(float lo, float hi) {
  uint32_t r;
  asm("cvt.rn.f16x2.f32 %0, %1, %2;" : "=r"(r) : "f"(hi), "f"(lo));
  return r;
}

__device__ __forceinline__ uint32_t sw128(uint32_t off) {
  return off ^ ((off >> 3) & 0x70);
}

__device__ __forceinline__ void ldsm_x4(uint32_t* r, uint32_t addr) {
  asm volatile("ldmatrix.sync.aligned.m8n8.x4.shared.b16 {%0,%1,%2,%3}, [%4];"
               : "=r"(r[0]), "=r"(r[1]), "=r"(r[2]), "=r"(r[3]) : "r"(addr));
}

__device__ __forceinline__ void ldsm_x4_trans(uint32_t* r, uint32_t addr) {
  asm volatile("ldmatrix.sync.aligned.m8n8.x4.trans.shared.b16 {%0,%1,%2,%3}, [%4];"
               : "=r"(r[0]), "=r"(r[1]), "=r"(r[2]), "=r"(r[3]) : "r"(addr));
}

__device__ __forceinline__ void mma_f16(float* c, const uint32_t* a,
                                        uint32_t b0, uint32_t b1) {
  asm volatile(
      "mma.sync.aligned.m16n8k16.row.col.f32.f16.f16.f32 "
      "{%0,%1,%2,%3}, {%4,%5,%6,%7}, {%8,%9}, {%0,%1,%2,%3};"
      : "+f"(c[0]), "+f"(c[1]), "+f"(c[2]), "+f"(c[3])
      : "r"(a[0]), "r"(a[1]), "r"(a[2]), "r"(a[3]), "r"(b0), "r"(b1));
}

__device__ __forceinline__ void cp16(uint32_t smem_addr, const void* gmem,
                                     uint32_t src_bytes) {
  asm volatile("cp.async.cg.shared.global [%0], [%1], 16, %2;"
               :: "r"(smem_addr), "l"(gmem), "r"(src_bytes) : "memory");
}

#define CP_COMMIT() asm volatile("cp.async.commit_group;" ::: "memory")
#define CP_WAIT0()  asm volatile("cp.async.wait_group 0;" ::: "memory")

// ---------------------------------------------------------------------------
// Kernel 1: x -> fp16
// ---------------------------------------------------------------------------

__global__ void __launch_bounds__(256) convert_x_kernel(const float* __restrict__ x) {
  const size_t g = (size_t)blockIdx.x * 256 + threadIdx.x;
  const float4 v = *(const float4*)(x + g * 4);
  uint2 o;
  o.x = pack_f16x2(v.x, v.y);
  o.y = pack_f16x2(v.z, v.w);
  *(uint2*)(&g_xh[g * 4]) = o;
}

// ---------------------------------------------------------------------------
// Kernel 2: streaming dequant, k-major in == k-major out, no smem.
// thread: 4 consecutive n, 8 consecutive k (one quant group slab).
// ---------------------------------------------------------------------------

__global__ void __launch_bounds__(256)
dequant_kernel(const int* __restrict__ qw, const float* __restrict__ snz) {
  const int tid = threadIdx.x;
  const int e  = blockIdx.z;
  const int k0 = blockIdx.x * 8;
  const int n  = (blockIdx.y * 256 + tid) * 4;
  const int g  = k0 >> 6;

  const float* sp = snz + (((size_t)e * kG + g) * kOUT + n) * 2;
  const float4 sa = *(const float4*)(sp);       // s0 z0 s1 z1
  const float4 sb = *(const float4*)(sp + 4);   // s2 z2 s3 z3
  const float s0 = sa.x, zp0 = fmaf(-8.f, sa.x, sa.y);
  const float s1 = sa.z, zp1 = fmaf(-8.f, sa.z, sa.w);
  const float s2 = sb.x, zp2 = fmaf(-8.f, sb.x, sb.y);
  const float s3 = sb.z, zp3 = fmaf(-8.f, sb.z, sb.w);

#pragma unroll
  for (int j = 0; j < 8; j++) {
    const size_t row = (size_t)e * kIN + k0 + j;
    const int4 q = *(const int4*)(qw + row * kOUT + n);
    uint2 o;
    o.x = pack_f16x2(fmaf((float)q.x, s0, zp0), fmaf((float)q.y, s1, zp1));
    o.y = pack_f16x2(fmaf((float)q.z, s2, zp2), fmaf((float)q.w, s3, zp3));
    *(uint2*)(&g_W[row * kOUT + n]) = o;
  }
}

// ---------------------------------------------------------------------------
// Kernel 3: main GEMM
// ---------------------------------------------------------------------------

__global__ void __launch_bounds__(kThreads, 2)
hqq_mma_kernel(const int* __restrict__ tpe, float* __restrict__ out) {
  extern __shared__ __align__(1024) char smem[];
  const int tid = threadIdx.x;
  const int wid = tid >> 5;
  const int l   = tid & 31;

  const int e  = blockIdx.z;
  const int nt = blockIdx.x;
  const int mt = blockIdx.y;

  int off = 0, cnt = 0;
#pragma unroll
  for (int i = 0; i < kE; i++) {
    int c = __ldg(&tpe[i]);
    if (i < e) off += c;
    if (i == e) cnt = c;
  }
  if (mt * kBM >= cnt) return;

  const int row0  = off + mt * kBM;
  const int nrows = min(kBM, cnt - mt * kBM);
  const int n0    = nt * kBN;

  const uint32_t sbase = smem_u32(smem);

  // ---- fragment addressing (warp grid 2x4, warp tile 32x64) ----
  const int wm = wid >> 2;                 // 0..1
  const int wn = wid & 3;                  // 0..3
  const int rowA0 = wm * 32 + (l & 15);
  const int segA  = l >> 4;
  // B trans-ldsm lane mapping: g = l>>3 -> (k-half, n-half); j = l&7 = k row low
  const int bj    = l & 7;
  const int bkoff = ((l >> 3) & 1) * 8 + bj;     // k row within 16-k step
  const int bnoff = (l >> 4);                    // n-chunk offset (0 or 1)

  const __half* xh_base = &g_xh[0];
  const __half* w_base  = &g_W[(size_t)e * kIN * kOUT];

  auto issue_stage = [&](int ch, int buf) {
    const int k0 = ch * kBK;
    const uint32_t st = sbase + buf * kStageB;
    // A: 512 segs, rows m (128B of k), sw128
#pragma unroll
    for (int i = 0; i < 2; i++) {
      const int g = i * 256 + tid;
      const int m = g >> 3, kseg = g & 7;
      cp16(st + sw128((uint32_t)(m * 128 + kseg * 16)),
           xh_base + (size_t)(row0 + m) * kIN + k0 + kseg * 8,
           (m < nrows) ? 16u : 0u);
    }
    // B: 2048 segs, rows k (512B of n), chunk-XOR swizzle
    const uint32_t stB = st + kATileB;
#pragma unroll
    for (int i = 0; i < 8; i++) {
      const int g = i * 256 + tid;
      const int krow = g >> 5, nchunk = g & 31;
      cp16(stB + (uint32_t)(krow * kBRowB + ((nchunk ^ (krow & 7)) * 16)),
           w_base + (size_t)(k0 + krow) * kOUT + n0 + nchunk * 8, 16u);
    }
    CP_COMMIT();
  };

  float mast[64];
#pragma unroll
  for (int i = 0; i < 64; i++) mast[i] = 0.f;

  issue_stage(0, 0);

  for (int ch = 0; ch < kNCh; ch++) {
    const int buf = ch & 1;
    CP_WAIT0();
    __syncthreads();
    if (ch + 1 < kNCh) issue_stage(ch + 1, buf ^ 1);

    const uint32_t base  = sbase + buf * kStageB;
    const uint32_t baseB = base + kATileB;
#pragma unroll
    for (int ks = 0; ks < 4; ks++) {        // 16-k steps
      uint32_t Af[2][4];
#pragma unroll
      for (int mi = 0; mi < 2; mi++) {
        const int row = rowA0 + mi * 16;
        ldsm_x4(Af[mi], base + (uint32_t)(row * 128) +
                         (((uint32_t)(ks * 32 + segA * 16)) ^ ((row & 7) << 4)));
      }
#pragma unroll
      for (int ni2 = 0; ni2 < 4; ni2++) {   // 16-n blocks of the 64-n warp tile
        // trans x4: g0=(k-lo,n-lo)->b0  g1=(k-hi,n-lo)->b1  g2,g3 = n-hi
        const int krow   = ks * 16 + bkoff;
        const int nchunk = wn * 8 + ni2 * 2 + bnoff;
        uint32_t r[4];
        ldsm_x4_trans(r, baseB + (uint32_t)(krow * kBRowB +
                                            ((nchunk ^ bj) * 16)));
#pragma unroll
        for (int mi = 0; mi < 2; mi++) {
          mma_f16(&mast[(mi * 8 + ni2 * 2) * 4],     Af[mi], r[0], r[1]);
          mma_f16(&mast[(mi * 8 + ni2 * 2 + 1) * 4], Af[mi], r[2], r[3]);
        }
      }
    }
  }

  // ---- epilogue ----
#pragma unroll
  for (int mi = 0; mi < 2; mi++) {
#pragma unroll
    for (int ni = 0; ni < 8; ni++) {
      const float* c = &mast[(mi * 8 + ni) * 4];
      const int r0  = wm * 32 + mi * 16 + (l >> 2);
      const int col = n0 + wn * 64 + ni * 8 + (l & 3) * 2;
      if (r0 < nrows)
        *(float2*)(out + (size_t)(row0 + r0) * kOUT + col) = make_float2(c[0], c[1]);
      if (r0 + 8 < nrows)
        *(float2*)(out + (size_t)(row0 + r0 + 8) * kOUT + col) = make_float2(c[2], c[3]);
    }
  }
}

}  // namespace

// ---------------------------------------------------------------------------

extern "C" void kernel_launch(void* const* d_in, const int* in_sizes, int n_in,
                              void* d_out, int out_size) {
  (void)in_sizes; (void)n_in; (void)out_size;
  const float* x   = (const float*)d_in[0];
  const int*   qw  = (const int*)d_in[1];
  const float* snz = (const float*)d_in[2];
  const int*   tpe = (const int*)d_in[3];
  float* out = (float*)d_out;

  (void)cudaFuncSetAttribute(hqq_mma_kernel,
                             cudaFuncAttributeMaxDynamicSharedMemorySize, kSmemB);

  convert_x_kernel<<<(kT * kIN) / (256 * 4), 256>>>(x);
  dequant_kernel<<<dim3(kIN / 8, kOUT / 1024, kE), 256>>>(qw, snz);
  dim3 grid(kOUT / kBN, kT / kBM, kE);   // (8, 32, 8); empty m-tiles early-exit
  hqq_mma_kernel<<<grid, kThreads, kSmemB>>>(tpe, out);
}

// round 14
// speedup vs baseline: 3.6618x; 1.0285x over previous
#include <cuda_runtime.h>
#include <cuda_fp16.h>
#include <cstdint>

// ============================================================================
// HQQ grouped int4 GEMM, sm_103 base target.
//
// R14: two-kernel graph:
//   1. prep   : (merged) xh = fp16(x)  AND  W[e][k][n] = fp16(q*s + z - 8s)
//               one grid, both pure streaming, no smem.
//   2. main   : 64x256 CTA tile, 32x64 warp tiles, cp.async 2-stage,
//               A normal ldsm, B ldmatrix.trans, ch-loop unrolled x2 with
//               hoisted address invariants.
// ============================================================================

namespace {

constexpr int kE   = 8;
constexpr int kT   = 2048;
constexpr int kIN  = 2048;
constexpr int kOUT = 2048;
constexpr int kG   = 32;

constexpr int kBM  = 64;
constexpr int kBN  = 256;
constexpr int kBK  = 64;
constexpr int kNCh = kIN / kBK;           // 32
constexpr int kThreads = 256;             // 8 warps, grid 2(m) x 4(n)

constexpr int kATileB = kBM * kBK * 2;    // 8 KB
constexpr int kBRowB  = kBN * 2;          // 512B per k-row
constexpr int kBTileB = kBK * kBRowB;     // 32 KB
constexpr int kStageB = kATileB + kBTileB;          // 40960
constexpr int kSmemB  = 2 * kStageB;                // 81920

// prep grid split
constexpr int kDqBlocks = kE * (kIN / 8) * (kOUT / 1024);  // 4096
constexpr int kCvBlocks = (kT * kIN) / (256 * 16);         // 1024

__device__ __half g_xh[(size_t)kT * kIN];
__device__ __half g_W[(size_t)kE * kIN * kOUT];     // k-major, same layout as q

// ---------------------------------------------------------------------------

__device__ __forceinline__ uint32_t smem_u32(const void* p) {
  uint32_t a;
  asm("{ .reg .u64 t; cvta.to.shared.u64 t, %1; cvt.u32.u64 %0, t; }" : "=r"(a) : "l"(p));
  return a;
}

__device__ __forceinline__ uint32_t pack_f16x2(float lo, float hi) {
  uint32_t r;
  asm("cvt.rn.f16x2.f32 %0, %1, %2;" : "=r"(r) : "f"(hi), "f"(lo));
  return r;
}

__device__ __forceinline__ uint32_t sw128(uint32_t off) {
  return off ^ ((off >> 3) & 0x70);
}

__device__ __forceinline__ void ldsm_x4(uint32_t* r, uint32_t addr) {
  asm volatile("ldmatrix.sync.aligned.m8n8.x4.shared.b16 {%0,%1,%2,%3}, [%4];"
               : "=r"(r[0]), "=r"(r[1]), "=r"(r[2]), "=r"(r[3]) : "r"(addr));
}

__device__ __forceinline__ void ldsm_x4_trans(uint32_t* r, uint32_t addr) {
  asm volatile("ldmatrix.sync.aligned.m8n8.x4.trans.shared.b16 {%0,%1,%2,%3}, [%4];"
               : "=r"(r[0]), "=r"(r[1]), "=r"(r[2]), "=r"(r[3]) : "r"(addr));
}

__device__ __forceinline__ void mma_f16(float* c, const uint32_t* a,
                                        uint32_t b0, uint32_t b1) {
  asm volatile(
      "mma.sync.aligned.m16n8k16.row.col.f32.f16.f16.f32 "
      "{%0,%1,%2,%3}, {%4,%5,%6,%7}, {%8,%9}, {%0,%1,%2,%3};"
      : "+f"(c[0]), "+f"(c[1]), "+f"(c[2]), "+f"(c[3])
      : "r"(a[0]), "r"(a[1]), "r"(a[2]), "r"(a[3]), "r"(b0), "r"(b1));
}

__device__ __forceinline__ void cp16(uint32_t smem_addr, const void* gmem,
                                     uint32_t src_bytes) {
  asm volatile("cp.async.cg.shared.global [%0], [%1], 16, %2;"
               :: "r"(smem_addr), "l"(gmem), "r"(src_bytes) : "memory");
}

#define CP_COMMIT() asm volatile("cp.async.commit_group;" ::: "memory")
#define CP_WAIT0()  asm volatile("cp.async.wait_group 0;" ::: "memory")

// ---------------------------------------------------------------------------
// Kernel 1: merged prepass.  Blocks [0, kDqBlocks): dequant; rest: convert x.
// ---------------------------------------------------------------------------

__global__ void __launch_bounds__(256)
prep_kernel(const float* __restrict__ x, const int* __restrict__ qw,
            const float* __restrict__ snz) {
  const int tid = threadIdx.x;
  const int b   = blockIdx.x;

  if (b < kDqBlocks) {
    // ---- dequant: thread = 4 consecutive n, 8 consecutive k ----
    const int e   = b >> 9;
    const int rem = b & 511;
    const int k0  = (rem >> 1) * 8;
    const int n   = ((rem & 1) * 256 + tid) * 4;
    const int g   = k0 >> 6;

    const float* sp = snz + (((size_t)e * kG + g) * kOUT + n) * 2;
    const float4 sa = *(const float4*)(sp);
    const float4 sb = *(const float4*)(sp + 4);
    const float s0 = sa.x, zp0 = fmaf(-8.f, sa.x, sa.y);
    const float s1 = sa.z, zp1 = fmaf(-8.f, sa.z, sa.w);
    const float s2 = sb.x, zp2 = fmaf(-8.f, sb.x, sb.y);
    const float s3 = sb.z, zp3 = fmaf(-8.f, sb.z, sb.w);

#pragma unroll
    for (int j = 0; j < 8; j++) {
      const size_t row = (size_t)e * kIN + k0 + j;
      const int4 q = *(const int4*)(qw + row * kOUT + n);
      uint2 o;
      o.x = pack_f16x2(fmaf((float)q.x, s0, zp0), fmaf((float)q.y, s1, zp1));
      o.y = pack_f16x2(fmaf((float)q.z, s2, zp2), fmaf((float)q.w, s3, zp3));
      *(uint2*)(&g_W[row * kOUT + n]) = o;
    }
  } else {
    // ---- convert x: thread = 4 float4 segs (16 floats) ----
    const size_t base = ((size_t)(b - kDqBlocks) * 256 + tid) * 16;
#pragma unroll
    for (int i = 0; i < 4; i++) {
      const float4 v = *(const float4*)(x + base + i * 4);
      uint2 o;
      o.x = pack_f16x2(v.x, v.y);
      o.y = pack_f16x2(v.z, v.w);
      *(uint2*)(&g_xh[base + i * 4]) = o;
    }
  }
}

// ---------------------------------------------------------------------------
// Kernel 2: main GEMM
// ---------------------------------------------------------------------------

__global__ void __launch_bounds__(kThreads, 2)
hqq_mma_kernel(const int* __restrict__ tpe, float* __restrict__ out) {
  extern __shared__ __align__(1024) char smem[];
  const int tid = threadIdx.x;
  const int wid = tid >> 5;
  const int l   = tid & 31;

  const int e  = blockIdx.z;
  const int nt = blockIdx.x;
  const int mt = blockIdx.y;

  int off = 0, cnt = 0;
#pragma unroll
  for (int i = 0; i < kE; i++) {
    int c = __ldg(&tpe[i]);
    if (i < e) off += c;
    if (i == e) cnt = c;
  }
  if (mt * kBM >= cnt) return;

  const int row0  = off + mt * kBM;
  const int nrows = min(kBM, cnt - mt * kBM);
  const int n0    = nt * kBN;

  const uint32_t sbase = smem_u32(smem);

  // ---- fragment addressing (warp grid 2x4, warp tile 32x64) ----
  const int wm = wid >> 2;
  const int wn = wid & 3;
  const int segA = l >> 4;
  const int bj   = l & 7;

  // hoisted A-ldsm invariants: per mi, row term + XOR
  uint32_t aRow[2], aXor[2];
#pragma unroll
  for (int mi = 0; mi < 2; mi++) {
    const int row = wm * 32 + (l & 15) + mi * 16;
    aRow[mi] = (uint32_t)(row * 128);
    aXor[mi] = (uint32_t)(((row & 7) << 4));
  }
  const uint32_t aSeg = (uint32_t)(segA * 16);

  // hoisted B-ldsm invariants: base = bkoff*512; per ni2 chunk offsets
  const int bkoff = ((l >> 3) & 1) * 8 + bj;
  const uint32_t bBase = (uint32_t)(bkoff * kBRowB);
  uint32_t bChunk[4];
#pragma unroll
  for (int ni2 = 0; ni2 < 4; ni2++)
    bChunk[ni2] = (uint32_t)(((wn * 8 + ni2 * 2 + (l >> 4)) ^ bj) * 16);

  const __half* xh_base = &g_xh[0];
  const __half* w_base  = &g_W[(size_t)e * kIN * kOUT];

  // hoisted cp.async invariants
  const int cpAm = tid >> 3, cpAk = tid & 3;     // A: 2 segs/thread via i
  const int cpBn = tid >> 5, cpBc = tid & 31;    // B: 8 segs/thread via i

  auto issue_stage = [&](int ch, uint32_t st) {
    const int k0 = ch * kBK;
#pragma unroll
    for (int i = 0; i < 2; i++) {
      const int m = cpAm + i * 32;
      const int kseg = cpAk + (0) * 4;   // segs 0..3 for i=0? no: A needs 8 segs per row
      (void)kseg;
      // A: 512 segs: g = i*256+tid -> m = g>>3, ks8 = g&7
      const int g = i * 256 + tid;
      const int mm = g >> 3, ks8 = g & 7;
      cp16(st + sw128((uint32_t)(mm * 128 + ks8 * 16)),
           xh_base + (size_t)(row0 + mm) * kIN + k0 + ks8 * 8,
           (mm < nrows) ? 16u : 0u);
    }
    const uint32_t stB = st + kATileB;
#pragma unroll
    for (int i = 0; i < 8; i++) {
      const int g = i * 256 + tid;
      const int krow = g >> 5, nchunk = g & 31;
      cp16(stB + (uint32_t)(krow * kBRowB + ((nchunk ^ (krow & 7)) * 16)),
           w_base + (size_t)(k0 + krow) * kOUT + n0 + nchunk * 8, 16u);
    }
    CP_COMMIT();
  };

  float mast[64];
#pragma unroll
  for (int i = 0; i < 64; i++) mast[i] = 0.f;

  auto compute_stage = [&](uint32_t base) {
    const uint32_t baseB = base + kATileB + bBase;
#pragma unroll
    for (int ks = 0; ks < 4; ks++) {
      uint32_t Af[2][4];
      const uint32_t kterm = (uint32_t)(ks * 32) + aSeg;
#pragma unroll
      for (int mi = 0; mi < 2; mi++)
        ldsm_x4(Af[mi], base + aRow[mi] + (kterm ^ aXor[mi]));
      const uint32_t bK = baseB + (uint32_t)(ks * 16 * kBRowB);
#pragma unroll
      for (int ni2 = 0; ni2 < 4; ni2++) {
        uint32_t r[4];
        ldsm_x4_trans(r, bK + bChunk[ni2]);
#pragma unroll
        for (int mi = 0; mi < 2; mi++) {
          mma_f16(&mast[(mi * 8 + ni2 * 2) * 4],     Af[mi], r[0], r[1]);
          mma_f16(&mast[(mi * 8 + ni2 * 2 + 1) * 4], Af[mi], r[2], r[3]);
        }
      }
    }
  };

  const uint32_t st0 = sbase;
  const uint32_t st1 = sbase + kStageB;

  issue_stage(0, st0);
  // unrolled x2: buf roles constant per body
  for (int ch = 0; ch < kNCh; ch += 2) {
    CP_WAIT0();
    __syncthreads();
    if (ch + 1 < kNCh) issue_stage(ch + 1, st1);
    compute_stage(st0);

    CP_WAIT0();
    __syncthreads();
    if (ch + 2 < kNCh) issue_stage(ch + 2, st0);
    compute_stage(st1);
  }

  // ---- epilogue ----
#pragma unroll
  for (int mi = 0; mi < 2; mi++) {
#pragma unroll
    for (int ni = 0; ni < 8; ni++) {
      const float* c = &mast[(mi * 8 + ni) * 4];
      const int r0  = wm * 32 + mi * 16 + (l >> 2);
      const int col = n0 + wn * 64 + ni * 8 + (l & 3) * 2;
      if (r0 < nrows)
        *(float2*)(out + (size_t)(row0 + r0) * kOUT + col) = make_float2(c[0], c[1]);
      if (r0 + 8 < nrows)
        *(float2*)(out + (size_t)(row0 + r0 + 8) * kOUT + col) = make_float2(c[2], c[3]);
    }
  }
}

}  // namespace

// ---------------------------------------------------------------------------

extern "C" void kernel_launch(void* const* d_in, const int* in_sizes, int n_in,
                              void* d_out, int out_size) {
  (void)in_sizes; (void)n_in; (void)out_size;
  const float* x   = (const float*)d_in[0];
  const int*   qw  = (const int*)d_in[1];
  const float* snz = (const float*)d_in[2];
  const int*   tpe = (const int*)d_in[3];
  float* out = (float*)d_out;

  (void)cudaFuncSetAttribute(hqq_mma_kernel,
                             cudaFuncAttributeMaxDynamicSharedMemorySize, kSmemB);

  prep_kernel<<<kDqBlocks + kCvBlocks, 256>>>(x, qw, snz);
  dim3 grid(kOUT / kBN, kT / kBM, kE);   // (8, 32, 8); empty m-tiles early-exit
  hqq_mma_kernel<<<grid, kThreads, kSmemB>>>(tpe, out);
}